// round 3
// baseline (speedup 1.0000x reference)
#include <cuda_runtime.h>

#define N_NODES 100000
#define N_EDGES 1600000
#define C_HID   128
#define E_DIM   32
#define C_OUT   64
#define N_LAYERS 4

typedef unsigned long long ull;

// ---------------- scratch (static device globals; no allocation) ----------------
__device__ float g_x  [(size_t)N_NODES * C_HID];   // 51.2 MB, current node features
__device__ float g_agg[(size_t)N_NODES * C_HID];   // 51.2 MB, per-layer aggregation
__device__ int   g_idx64_flag;

// ---------------- packed fp32 helpers (sm_103a f32x2 pipe: 2x FFMA rate) --------
__device__ __forceinline__ ull pack2(float x, float y) {
    ull r; asm("mov.b64 %0, {%1, %2};" : "=l"(r) : "f"(x), "f"(y)); return r;
}
__device__ __forceinline__ float2 unpack2(ull v) {
    float2 r; asm("mov.b64 {%0, %1}, %2;" : "=f"(r.x), "=f"(r.y) : "l"(v)); return r;
}
__device__ __forceinline__ void fma2(ull& acc, ull a, ull b) {
    asm("fma.rn.f32x2 %0, %1, %2, %0;" : "+l"(acc) : "l"(a), "l"(b));
}
__device__ __forceinline__ void red4(float* p, float4 v) {
    asm volatile("red.global.add.v4.f32 [%0], {%1, %2, %3, %4};"
                 :: "l"(p), "f"(v.x), "f"(v.y), "f"(v.z), "f"(v.w) : "memory");
}

// ---------------- dtype probe: edge_index int64 vs int32 ------------------------
// If int64 (values < 2^31, nonneg), every odd int32 word of the buffer is 0.
__global__ void probe_kernel(const int* __restrict__ ei) {
    if (threadIdx.x == 0 && blockIdx.x == 0) {
        int all0 = 1;
        for (int i = 1; i < 64; i += 2) all0 &= (ei[i] == 0);
        g_idx64_flag = all0;
    }
}

// ---------------- edge kernel ----------------------------------------------------
// Per warp-iteration: 2 edges. e = edge_attr@We + be (E_DIM=32 matvec via f32x2),
// msg = relu(x[src] + e), red.v4 into agg[dst]. lane owns channels 4*lane..4*lane+3.
__global__ void __launch_bounds__(256) edge_kernel(
    const float* __restrict__ ea, const void* __restrict__ ei_raw,
    const float* __restrict__ x, const float* __restrict__ We,
    const float* __restrict__ be, float* __restrict__ agg, int layer)
{
    __shared__ float4 Ws[E_DIM * 32];   // [k][lane] = We[k][4*lane..4*lane+3], 16KB
    __shared__ float  bes[C_HID];

    const float4* We4 = (const float4*)(We + (size_t)layer * E_DIM * C_HID);
    for (int i = threadIdx.x; i < E_DIM * 32; i += 256) Ws[i] = We4[i];
    if (threadIdx.x < C_HID) bes[threadIdx.x] = be[layer * C_HID + threadIdx.x];
    __syncthreads();

    const int use64 = g_idx64_flag;
    const long long* ei64 = (const long long*)ei_raw;
    const int*       ei32 = (const int*)ei_raw;
    const float4*    x4   = (const float4*)x;
    const ulonglong2* Ws2 = (const ulonglong2*)Ws;

    const int lane   = threadIdx.x & 31;
    const int warp   = (blockIdx.x * blockDim.x + threadIdx.x) >> 5;
    const int nwarps = (gridDim.x * blockDim.x) >> 5;

    const ull be01 = pack2(bes[lane * 4 + 0], bes[lane * 4 + 1]);
    const ull be23 = pack2(bes[lane * 4 + 2], bes[lane * 4 + 3]);

    for (int p = warp; p < N_EDGES / 2; p += nwarps) {
        const int e0 = 2 * p, e1 = 2 * p + 1;
        const float a0 = ea[e0 * E_DIM + lane];
        const float a1 = ea[e1 * E_DIM + lane];

        int s0, d0, s1, d1;
        if (use64) {
            s0 = (int)ei64[e0];           s1 = (int)ei64[e1];
            d0 = (int)ei64[N_EDGES + e0]; d1 = (int)ei64[N_EDGES + e1];
        } else {
            s0 = ei32[e0];                s1 = ei32[e1];
            d0 = ei32[N_EDGES + e0];      d1 = ei32[N_EDGES + e1];
        }

        ull acc0a = be01, acc0b = be23, acc1a = be01, acc1b = be23;
        #pragma unroll
        for (int k = 0; k < E_DIM; k++) {
            const float ak0 = __shfl_sync(0xffffffffu, a0, k);
            const float ak1 = __shfl_sync(0xffffffffu, a1, k);
            const ull av0 = pack2(ak0, ak0);
            const ull av1 = pack2(ak1, ak1);
            const ulonglong2 w = Ws2[k * 32 + lane];   // {w_c0,w_c1},{w_c2,w_c3}
            fma2(acc0a, av0, w.x); fma2(acc0b, av0, w.y);
            fma2(acc1a, av1, w.x); fma2(acc1b, av1, w.y);
        }

        const float4 xv0 = x4[s0 * 32 + lane];
        const float4 xv1 = x4[s1 * 32 + lane];
        float2 p0 = unpack2(acc0a), q0 = unpack2(acc0b);
        float2 p1 = unpack2(acc1a), q1 = unpack2(acc1b);
        float4 m0, m1;
        m0.x = fmaxf(p0.x + xv0.x, 0.f); m0.y = fmaxf(p0.y + xv0.y, 0.f);
        m0.z = fmaxf(q0.x + xv0.z, 0.f); m0.w = fmaxf(q0.y + xv0.w, 0.f);
        m1.x = fmaxf(p1.x + xv1.x, 0.f); m1.y = fmaxf(p1.y + xv1.y, 0.f);
        m1.z = fmaxf(q1.x + xv1.z, 0.f); m1.w = fmaxf(q1.y + xv1.w, 0.f);
        red4(agg + (size_t)d0 * C_HID + lane * 4, m0);
        red4(agg + (size_t)d1 * C_HID + lane * 4, m1);
    }
}

// ---------------- node kernel -----------------------------------------------------
// Per block: 32 nodes. h0 = x + agg; y = relu(h0@W1+b1); h2 = y@W2+b2; LN;
// x = relu(h2_ln + x_res). Transposed smem tiles so node pairs load as packed f32x2.
#define H0P 36                       // padded row stride (floats), 16B-aligned rows
#define YP  36
#define SM_H0T 0                     // 128*36 = 4608 floats (aliased by h2s: 32*132)
#define SM_YT  4608                  // 256*36 = 9216 floats
#define SM_WSL (4608 + 9216)         // 8192 floats
#define NODE_SMEM ((4608 + 9216 + 8192) * 4)

__global__ void __launch_bounds__(256) node_kernel(
    float* __restrict__ x, const float* __restrict__ agg,
    const float* __restrict__ W1, const float* __restrict__ b1,
    const float* __restrict__ W2, const float* __restrict__ b2,
    const float* __restrict__ lnw, const float* __restrict__ lnb, int layer)
{
    extern __shared__ float sm[];
    float* h0T = sm + SM_H0T;
    float* h2s = sm + SM_H0T;        // alias: h0T dead after phase B
    float* yT  = sm + SM_YT;
    float* Wsl = sm + SM_WSL;

    const int tid = threadIdx.x;
    const int n0  = blockIdx.x * 32;

    // ---- Phase A: h0T[k][n] = x[n][k] + agg[n][k] (transposed) ----
    {
        const float4* x4 = (const float4*)x   + (size_t)n0 * 32;
        const float4* a4 = (const float4*)agg + (size_t)n0 * 32;
        #pragma unroll
        for (int j = 0; j < 4; j++) {
            const int idx = tid + j * 256;           // 0..1023 float4s
            const int node = idx >> 5, kq = idx & 31;
            const float4 xv = x4[node * 32 + kq];
            const float4 av = a4[node * 32 + kq];
            const int kb = kq * 4;
            h0T[(kb + 0) * H0P + node] = xv.x + av.x;
            h0T[(kb + 1) * H0P + node] = xv.y + av.y;
            h0T[(kb + 2) * H0P + node] = xv.z + av.z;
            h0T[(kb + 3) * H0P + node] = xv.w + av.w;
        }
    }

    // ---- Phase B: y[n][c] = relu(sum_k h0[n][k] * W1[k][c] + b1[c]); col c = tid ----
    {
        ull acc[16];
        const float bb = b1[layer * 256 + tid];
        const ull bp = pack2(bb, bb);
        #pragma unroll
        for (int q = 0; q < 16; q++) acc[q] = bp;

        const float4* W1g = (const float4*)(W1 + (size_t)layer * 128 * 256);
        for (int s = 0; s < 4; s++) {               // k-slabs of 32
            __syncthreads();
            #pragma unroll
            for (int i = 0; i < 8; i++)
                ((float4*)Wsl)[tid + i * 256] = W1g[s * 2048 + tid + i * 256];
            __syncthreads();
            #pragma unroll 8
            for (int k = 0; k < 32; k++) {
                const float w = Wsl[k * 256 + tid];
                const ull w2 = pack2(w, w);
                const ulonglong2* hr = (const ulonglong2*)(h0T + (s * 32 + k) * H0P);
                #pragma unroll
                for (int pp = 0; pp < 8; pp++) {
                    const ulonglong2 hv = hr[pp];   // nodes {4p,4p+1},{4p+2,4p+3}
                    fma2(acc[2 * pp + 0], hv.x, w2);
                    fma2(acc[2 * pp + 1], hv.y, w2);
                }
            }
        }
        float* yrow = yT + tid * YP;                // yT[c][n]
        #pragma unroll
        for (int q = 0; q < 16; q++) {
            const float2 v = unpack2(acc[q]);
            yrow[2 * q + 0] = fmaxf(v.x, 0.f);
            yrow[2 * q + 1] = fmaxf(v.y, 0.f);
        }
    }

    // ---- Phase C: h2[n][c] = sum_k y[n][k] * W2[k][c] + b2[c] ----
    const int col = tid & 127;
    const int nh  = tid >> 7;                        // node half: 16 nodes each
    {
        ull acc[8];
        const float bb = b2[layer * 128 + col];
        const ull bp = pack2(bb, bb);
        #pragma unroll
        for (int q = 0; q < 8; q++) acc[q] = bp;

        const float4* W2g = (const float4*)(W2 + (size_t)layer * 256 * 128);
        for (int s = 0; s < 4; s++) {               // k-slabs of 64
            __syncthreads();
            #pragma unroll
            for (int i = 0; i < 8; i++)
                ((float4*)Wsl)[tid + i * 256] = W2g[s * 2048 + tid + i * 256];
            __syncthreads();
            #pragma unroll 8
            for (int k = 0; k < 64; k++) {
                const float w = Wsl[k * 128 + col];
                const ull w2 = pack2(w, w);
                const ulonglong2* yr = (const ulonglong2*)(yT + (s * 64 + k) * YP + nh * 16);
                #pragma unroll
                for (int pp = 0; pp < 4; pp++) {
                    const ulonglong2 yv = yr[pp];
                    fma2(acc[2 * pp + 0], yv.x, w2);
                    fma2(acc[2 * pp + 1], yv.y, w2);
                }
            }
        }
        __syncthreads();                             // h0T fully dead -> safe to alias
        #pragma unroll
        for (int q = 0; q < 8; q++) {
            const float2 v = unpack2(acc[q]);
            const int n = nh * 16 + 2 * q;
            h2s[(n + 0) * 132 + col] = v.x;
            h2s[(n + 1) * 132 + col] = v.y;
        }
    }
    __syncthreads();

    // ---- Phase D: LayerNorm + residual + ReLU, write x in place ----
    {
        const int warp = tid >> 5, lane = tid & 31;
        const float4 w4 = ((const float4*)(lnw + layer * 128))[lane];
        const float4 bb4 = ((const float4*)(lnb + layer * 128))[lane];
        #pragma unroll
        for (int i = 0; i < 4; i++) {
            const int n = warp * 4 + i;
            const float4 h = *(const float4*)(h2s + n * 132 + lane * 4);
            float s  = h.x + h.y + h.z + h.w;
            float s2 = h.x * h.x + h.y * h.y + h.z * h.z + h.w * h.w;
            #pragma unroll
            for (int off = 16; off; off >>= 1) {
                s  += __shfl_xor_sync(0xffffffffu, s,  off);
                s2 += __shfl_xor_sync(0xffffffffu, s2, off);
            }
            const float mu  = s  * (1.f / 128.f);
            const float var = s2 * (1.f / 128.f) - mu * mu;
            const float rs  = rsqrtf(var + 1e-5f);
            const size_t gi = (size_t)(n0 + n) * 32 + lane;
            const float4 xr = ((const float4*)x)[gi];
            float4 o;
            o.x = fmaxf((h.x - mu) * rs * w4.x + bb4.x + xr.x, 0.f);
            o.y = fmaxf((h.y - mu) * rs * w4.y + bb4.y + xr.y, 0.f);
            o.z = fmaxf((h.z - mu) * rs * w4.z + bb4.z + xr.z, 0.f);
            o.w = fmaxf((h.w - mu) * rs * w4.w + bb4.w + xr.w, 0.f);
            ((float4*)x)[gi] = o;
        }
    }
}

// ---------------- output projection: out = x @ Wout + bout -------------------------
__global__ void __launch_bounds__(256) out_kernel(
    const float* __restrict__ x, const float* __restrict__ Wo,
    const float* __restrict__ bo, float* __restrict__ out)
{
    __shared__ float xs[32 * 128];    // 16KB
    __shared__ float Ws[128 * 64];    // 32KB
    const int tid = threadIdx.x;
    const size_t n0 = (size_t)blockIdx.x * 32;

    #pragma unroll
    for (int i = 0; i < 4; i++)
        ((float4*)xs)[tid + i * 256] = ((const float4*)x)[n0 * 32 + tid + i * 256];
    #pragma unroll
    for (int i = 0; i < 8; i++)
        ((float4*)Ws)[tid + i * 256] = ((const float4*)Wo)[tid + i * 256];
    __syncthreads();

    const int col = tid & 63, ng = tid >> 6;   // 4 groups x 8 nodes
    float acc[8];
    const float b = bo[col];
    #pragma unroll
    for (int j = 0; j < 8; j++) acc[j] = b;
    for (int k = 0; k < 128; k++) {
        const float w = Ws[k * 64 + col];
        #pragma unroll
        for (int j = 0; j < 8; j++)
            acc[j] = fmaf(xs[(ng * 8 + j) * 128 + k], w, acc[j]);
    }
    #pragma unroll
    for (int j = 0; j < 8; j++)
        out[(n0 + ng * 8 + j) * C_OUT + col] = acc[j];
}

// ---------------- launch ------------------------------------------------------------
extern "C" void kernel_launch(void* const* d_in, const int* in_sizes, int n_in,
                              void* d_out, int out_size) {
    (void)in_sizes; (void)n_in; (void)out_size;
    const float* x   = (const float*)d_in[0];
    const void*  ei  = d_in[1];
    const float* ea  = (const float*)d_in[2];
    const float* We  = (const float*)d_in[3];
    const float* be  = (const float*)d_in[4];
    const float* W1  = (const float*)d_in[5];
    const float* b1  = (const float*)d_in[6];
    const float* W2  = (const float*)d_in[7];
    const float* b2  = (const float*)d_in[8];
    const float* lnw = (const float*)d_in[9];
    const float* lnb = (const float*)d_in[10];
    const float* Wo  = (const float*)d_in[11];
    const float* bo  = (const float*)d_in[12];
    float* out = (float*)d_out;

    void *pgx = nullptr, *pagg = nullptr;
    cudaGetSymbolAddress(&pgx, g_x);
    cudaGetSymbolAddress(&pagg, g_agg);
    float* gx   = (float*)pgx;
    float* gagg = (float*)pagg;

    cudaFuncSetAttribute(node_kernel, cudaFuncAttributeMaxDynamicSharedMemorySize,
                         NODE_SMEM);

    probe_kernel<<<1, 32>>>((const int*)ei);
    cudaMemcpyAsync(gx, x, (size_t)N_NODES * C_HID * sizeof(float),
                    cudaMemcpyDeviceToDevice);

    for (int l = 0; l < N_LAYERS; l++) {
        cudaMemsetAsync(gagg, 0, (size_t)N_NODES * C_HID * sizeof(float));
        edge_kernel<<<1184, 256>>>(ea, ei, gx, We, be, gagg, l);
        node_kernel<<<N_NODES / 32, 256, NODE_SMEM>>>(gx, gagg, W1, b1, W2, b2,
                                                      lnw, lnb, l);
    }
    out_kernel<<<N_NODES / 32, 256>>>(gx, Wo, bo, out);
}

// round 4
// speedup vs baseline: 1.2675x; 1.2675x over previous
#include <cuda_runtime.h>

#define N_NODES 100000
#define N_EDGES 1600000
#define C_HID   128
#define E_DIM   32
#define C_OUT   64
#define N_LAYERS 4

typedef unsigned long long ull;

// ---------------- scratch (static device globals; no allocation) ----------------
__device__ float g_x  [(size_t)N_NODES * C_HID];   // 51.2 MB, current node features
__device__ float g_agg[(size_t)N_NODES * C_HID];   // 51.2 MB, per-layer aggregation
__device__ int   g_idx64_flag;

// ---------------- packed fp32 helpers (sm_103a f32x2 pipe: 2x FFMA rate) --------
__device__ __forceinline__ ull pack2(float x, float y) {
    ull r; asm("mov.b64 %0, {%1, %2};" : "=l"(r) : "f"(x), "f"(y)); return r;
}
__device__ __forceinline__ float2 unpack2(ull v) {
    float2 r; asm("mov.b64 {%0, %1}, %2;" : "=f"(r.x), "=f"(r.y) : "l"(v)); return r;
}
__device__ __forceinline__ void fma2(ull& acc, ull a, ull b) {
    asm("fma.rn.f32x2 %0, %1, %2, %0;" : "+l"(acc) : "l"(a), "l"(b));
}
__device__ __forceinline__ void red4(float* p, float4 v) {
    asm volatile("red.global.add.v4.f32 [%0], {%1, %2, %3, %4};"
                 :: "l"(p), "f"(v.x), "f"(v.y), "f"(v.z), "f"(v.w) : "memory");
}

// ---------------- dtype probe: edge_index int64 vs int32 ------------------------
__global__ void probe_kernel(const int* __restrict__ ei) {
    if (threadIdx.x == 0 && blockIdx.x == 0) {
        int all0 = 1;
        for (int i = 1; i < 64; i += 2) all0 &= (ei[i] == 0);
        g_idx64_flag = all0;
    }
}

// ---------------- edge kernel (v2: 8 edges per warp-iteration) -------------------
// Weight LDS amortized 4x vs v1 (1 LDS.128 per 16 fma2). Per edge: 64 fma2 instr,
// 1 scattered LDG.128 gather, 1 red.global.add.v4. Indices lane-split + shfl.
__global__ void __launch_bounds__(256) edge_kernel(
    const float* __restrict__ ea, const void* __restrict__ ei_raw,
    const float* __restrict__ x, const float* __restrict__ We,
    const float* __restrict__ be, float* __restrict__ agg, int layer)
{
    __shared__ float4 Ws[E_DIM * 32];   // [k][lane] = We[k][4*lane..4*lane+3], 16KB
    __shared__ float  bes[C_HID];

    const float4* We4 = (const float4*)(We + (size_t)layer * E_DIM * C_HID);
    for (int i = threadIdx.x; i < E_DIM * 32; i += 256) Ws[i] = We4[i];
    if (threadIdx.x < C_HID) bes[threadIdx.x] = be[layer * C_HID + threadIdx.x];
    __syncthreads();

    const int use64 = g_idx64_flag;
    const long long* ei64 = (const long long*)ei_raw;
    const int*       ei32 = (const int*)ei_raw;
    const float4*    x4   = (const float4*)x;
    const ulonglong2* Ws2 = (const ulonglong2*)Ws;

    const int lane   = threadIdx.x & 31;
    const int warp   = (blockIdx.x * blockDim.x + threadIdx.x) >> 5;
    const int nwarps = (gridDim.x * blockDim.x) >> 5;

    const ull be01 = pack2(bes[lane * 4 + 0], bes[lane * 4 + 1]);
    const ull be23 = pack2(bes[lane * 4 + 2], bes[lane * 4 + 3]);

    for (int p = warp; p < N_EDGES / 8; p += nwarps) {
        const int e0 = p * 8;

        // edge attrs: a[j] = ea[e0+j][lane], 8 coalesced 128B loads
        float a[8];
        #pragma unroll
        for (int j = 0; j < 8; j++) a[j] = ea[(e0 + j) * E_DIM + lane];

        // indices lane-split: lanes 0..7 load src[e0+lane], lanes 8..15 load
        // dst[e0+lane-8]; broadcast later via shfl.
        int sv = 0;
        if (lane < 16) {
            if (use64) {
                const long long* bp = (lane < 8) ? (ei64 + e0 + lane)
                                                 : (ei64 + N_EDGES + e0 + lane - 8);
                sv = (int)(*bp);
            } else {
                const int* bp = (lane < 8) ? (ei32 + e0 + lane)
                                           : (ei32 + N_EDGES + e0 + lane - 8);
                sv = *bp;
            }
        }

        ull accA[8], accB[8];
        #pragma unroll
        for (int j = 0; j < 8; j++) { accA[j] = be01; accB[j] = be23; }

        #pragma unroll 8
        for (int k = 0; k < E_DIM; k++) {
            const ulonglong2 w = Ws2[k * 32 + lane];   // {w_c0,w_c1},{w_c2,w_c3}
            #pragma unroll
            for (int j = 0; j < 8; j++) {
                const float ak = __shfl_sync(0xffffffffu, a[j], k);
                const ull av = pack2(ak, ak);
                fma2(accA[j], av, w.x);
                fma2(accB[j], av, w.y);
            }
        }

        #pragma unroll
        for (int j = 0; j < 8; j++) {
            const int s = __shfl_sync(0xffffffffu, sv, j);
            const int d = __shfl_sync(0xffffffffu, sv, 8 + j);
            const float4 xv = x4[(size_t)s * 32 + lane];
            const float2 pA = unpack2(accA[j]);
            const float2 pB = unpack2(accB[j]);
            float4 m;
            m.x = fmaxf(pA.x + xv.x, 0.f);
            m.y = fmaxf(pA.y + xv.y, 0.f);
            m.z = fmaxf(pB.x + xv.z, 0.f);
            m.w = fmaxf(pB.y + xv.w, 0.f);
            red4(agg + (size_t)d * C_HID + lane * 4, m);
        }
    }
}

// ---------------- node kernel -----------------------------------------------------
// Per block: 32 nodes. h0 = x + agg; y = relu(h0@W1+b1); h2 = y@W2+b2; LN;
// x = relu(h2_ln + x_res). Transposed smem tiles so node pairs load as packed f32x2.
#define H0P 36
#define YP  36
#define SM_H0T 0
#define SM_YT  4608
#define SM_WSL (4608 + 9216)
#define NODE_SMEM ((4608 + 9216 + 8192) * 4)

__global__ void __launch_bounds__(256) node_kernel(
    float* __restrict__ x, const float* __restrict__ agg,
    const float* __restrict__ W1, const float* __restrict__ b1,
    const float* __restrict__ W2, const float* __restrict__ b2,
    const float* __restrict__ lnw, const float* __restrict__ lnb, int layer)
{
    extern __shared__ float sm[];
    float* h0T = sm + SM_H0T;
    float* h2s = sm + SM_H0T;        // alias: h0T dead after phase B
    float* yT  = sm + SM_YT;
    float* Wsl = sm + SM_WSL;

    const int tid = threadIdx.x;
    const int n0  = blockIdx.x * 32;

    // ---- Phase A: h0T[k][n] = x[n][k] + agg[n][k] (transposed) ----
    {
        const float4* x4 = (const float4*)x   + (size_t)n0 * 32;
        const float4* a4 = (const float4*)agg + (size_t)n0 * 32;
        #pragma unroll
        for (int j = 0; j < 4; j++) {
            const int idx = tid + j * 256;
            const int node = idx >> 5, kq = idx & 31;
            const float4 xv = x4[node * 32 + kq];
            const float4 av = a4[node * 32 + kq];
            const int kb = kq * 4;
            h0T[(kb + 0) * H0P + node] = xv.x + av.x;
            h0T[(kb + 1) * H0P + node] = xv.y + av.y;
            h0T[(kb + 2) * H0P + node] = xv.z + av.z;
            h0T[(kb + 3) * H0P + node] = xv.w + av.w;
        }
    }

    // ---- Phase B: y[n][c] = relu(sum_k h0[n][k] * W1[k][c] + b1[c]); col c = tid ----
    {
        ull acc[16];
        const float bb = b1[layer * 256 + tid];
        const ull bp = pack2(bb, bb);
        #pragma unroll
        for (int q = 0; q < 16; q++) acc[q] = bp;

        const float4* W1g = (const float4*)(W1 + (size_t)layer * 128 * 256);
        for (int s = 0; s < 4; s++) {
            __syncthreads();
            #pragma unroll
            for (int i = 0; i < 8; i++)
                ((float4*)Wsl)[tid + i * 256] = W1g[s * 2048 + tid + i * 256];
            __syncthreads();
            #pragma unroll 8
            for (int k = 0; k < 32; k++) {
                const float w = Wsl[k * 256 + tid];
                const ull w2 = pack2(w, w);
                const ulonglong2* hr = (const ulonglong2*)(h0T + (s * 32 + k) * H0P);
                #pragma unroll
                for (int pp = 0; pp < 8; pp++) {
                    const ulonglong2 hv = hr[pp];
                    fma2(acc[2 * pp + 0], hv.x, w2);
                    fma2(acc[2 * pp + 1], hv.y, w2);
                }
            }
        }
        float* yrow = yT + tid * YP;
        #pragma unroll
        for (int q = 0; q < 16; q++) {
            const float2 v = unpack2(acc[q]);
            yrow[2 * q + 0] = fmaxf(v.x, 0.f);
            yrow[2 * q + 1] = fmaxf(v.y, 0.f);
        }
    }

    // ---- Phase C: h2[n][c] = sum_k y[n][k] * W2[k][c] + b2[c] ----
    const int col = tid & 127;
    const int nh  = tid >> 7;
    {
        ull acc[8];
        const float bb = b2[layer * 128 + col];
        const ull bp = pack2(bb, bb);
        #pragma unroll
        for (int q = 0; q < 8; q++) acc[q] = bp;

        const float4* W2g = (const float4*)(W2 + (size_t)layer * 256 * 128);
        for (int s = 0; s < 4; s++) {
            __syncthreads();
            #pragma unroll
            for (int i = 0; i < 8; i++)
                ((float4*)Wsl)[tid + i * 256] = W2g[s * 2048 + tid + i * 256];
            __syncthreads();
            #pragma unroll 8
            for (int k = 0; k < 64; k++) {
                const float w = Wsl[k * 128 + col];
                const ull w2 = pack2(w, w);
                const ulonglong2* yr = (const ulonglong2*)(yT + (s * 64 + k) * YP + nh * 16);
                #pragma unroll
                for (int pp = 0; pp < 4; pp++) {
                    const ulonglong2 yv = yr[pp];
                    fma2(acc[2 * pp + 0], yv.x, w2);
                    fma2(acc[2 * pp + 1], yv.y, w2);
                }
            }
        }
        __syncthreads();
        #pragma unroll
        for (int q = 0; q < 8; q++) {
            const float2 v = unpack2(acc[q]);
            const int n = nh * 16 + 2 * q;
            h2s[(n + 0) * 132 + col] = v.x;
            h2s[(n + 1) * 132 + col] = v.y;
        }
    }
    __syncthreads();

    // ---- Phase D: LayerNorm + residual + ReLU, write x in place ----
    {
        const int warp = tid >> 5, lane = tid & 31;
        const float4 w4  = ((const float4*)(lnw + layer * 128))[lane];
        const float4 bb4 = ((const float4*)(lnb + layer * 128))[lane];
        #pragma unroll
        for (int i = 0; i < 4; i++) {
            const int n = warp * 4 + i;
            const float4 h = *(const float4*)(h2s + n * 132 + lane * 4);
            float s  = h.x + h.y + h.z + h.w;
            float s2 = h.x * h.x + h.y * h.y + h.z * h.z + h.w * h.w;
            #pragma unroll
            for (int off = 16; off; off >>= 1) {
                s  += __shfl_xor_sync(0xffffffffu, s,  off);
                s2 += __shfl_xor_sync(0xffffffffu, s2, off);
            }
            const float mu  = s  * (1.f / 128.f);
            const float var = s2 * (1.f / 128.f) - mu * mu;
            const float rs  = rsqrtf(var + 1e-5f);
            const size_t gi = (size_t)(n0 + n) * 32 + lane;
            const float4 xr = ((const float4*)x)[gi];
            float4 o;
            o.x = fmaxf((h.x - mu) * rs * w4.x + bb4.x + xr.x, 0.f);
            o.y = fmaxf((h.y - mu) * rs * w4.y + bb4.y + xr.y, 0.f);
            o.z = fmaxf((h.z - mu) * rs * w4.z + bb4.z + xr.z, 0.f);
            o.w = fmaxf((h.w - mu) * rs * w4.w + bb4.w + xr.w, 0.f);
            ((float4*)x)[gi] = o;
        }
    }
}

// ---------------- output projection: out = x @ Wout + bout -------------------------
__global__ void __launch_bounds__(256) out_kernel(
    const float* __restrict__ x, const float* __restrict__ Wo,
    const float* __restrict__ bo, float* __restrict__ out)
{
    __shared__ float xs[32 * 128];
    __shared__ float Ws[128 * 64];
    const int tid = threadIdx.x;
    const size_t n0 = (size_t)blockIdx.x * 32;

    #pragma unroll
    for (int i = 0; i < 4; i++)
        ((float4*)xs)[tid + i * 256] = ((const float4*)x)[n0 * 32 + tid + i * 256];
    #pragma unroll
    for (int i = 0; i < 8; i++)
        ((float4*)Ws)[tid + i * 256] = ((const float4*)Wo)[tid + i * 256];
    __syncthreads();

    const int col = tid & 63, ng = tid >> 6;
    float acc[8];
    const float b = bo[col];
    #pragma unroll
    for (int j = 0; j < 8; j++) acc[j] = b;
    for (int k = 0; k < 128; k++) {
        const float w = Ws[k * 64 + col];
        #pragma unroll
        for (int j = 0; j < 8; j++)
            acc[j] = fmaf(xs[(ng * 8 + j) * 128 + k], w, acc[j]);
    }
    #pragma unroll
    for (int j = 0; j < 8; j++)
        out[(n0 + ng * 8 + j) * C_OUT + col] = acc[j];
}

// ---------------- launch ------------------------------------------------------------
extern "C" void kernel_launch(void* const* d_in, const int* in_sizes, int n_in,
                              void* d_out, int out_size) {
    (void)in_sizes; (void)n_in; (void)out_size;
    const float* x   = (const float*)d_in[0];
    const void*  ei  = d_in[1];
    const float* ea  = (const float*)d_in[2];
    const float* We  = (const float*)d_in[3];
    const float* be  = (const float*)d_in[4];
    const float* W1  = (const float*)d_in[5];
    const float* b1  = (const float*)d_in[6];
    const float* W2  = (const float*)d_in[7];
    const float* b2  = (const float*)d_in[8];
    const float* lnw = (const float*)d_in[9];
    const float* lnb = (const float*)d_in[10];
    const float* Wo  = (const float*)d_in[11];
    const float* bo  = (const float*)d_in[12];
    float* out = (float*)d_out;

    void *pgx = nullptr, *pagg = nullptr;
    cudaGetSymbolAddress(&pgx, g_x);
    cudaGetSymbolAddress(&pagg, g_agg);
    float* gx   = (float*)pgx;
    float* gagg = (float*)pagg;

    cudaFuncSetAttribute(node_kernel, cudaFuncAttributeMaxDynamicSharedMemorySize,
                         NODE_SMEM);

    probe_kernel<<<1, 32>>>((const int*)ei);
    cudaMemcpyAsync(gx, x, (size_t)N_NODES * C_HID * sizeof(float),
                    cudaMemcpyDeviceToDevice);

    for (int l = 0; l < N_LAYERS; l++) {
        cudaMemsetAsync(gagg, 0, (size_t)N_NODES * C_HID * sizeof(float));
        edge_kernel<<<1184, 256>>>(ea, ei, gx, We, be, gagg, l);
        node_kernel<<<N_NODES / 32, 256, NODE_SMEM>>>(gx, gagg, W1, b1, W2, b2,
                                                      lnw, lnb, l);
    }
    out_kernel<<<N_NODES / 32, 256>>>(gx, Wo, bo, out);
}